// round 4
// baseline (speedup 1.0000x reference)
#include <cuda_runtime.h>
#include <cuda_bf16.h>
#include <cuda_fp16.h>

#define N_MAX 100000
#define E_MAX 1600000
#define PAD 64   // max in-degree slot count (Poisson(16): P(>=64) ~ 2e-18)

// ---------------- device scratch ----------------
__device__ int    g_flag;                 // 1 = edge_index is int64
__device__ float  g_expsum[N_MAX];
__device__ int    g_fill[N_MAX];
__device__ float2 g_edge[N_MAX * PAD];    // {src_bits, exp(attr)} bucketed by dst
__device__ float  g_xw[N_MAX * 64];       // fp32 (self term + h1 path)
__device__ __half g_xwh[N_MAX * 64];      // fp16 copy (gather payload)
__device__ float  g_h1[N_MAX * 64];

// ---------------- f32x2 packed fma ----------------
__device__ __forceinline__ void ffma2(unsigned long long& d,
                                      unsigned long long a,
                                      unsigned long long b) {
    asm("fma.rn.f32x2 %0, %1, %2, %0;" : "+l"(d) : "l"(a), "l"(b));
}
__device__ __forceinline__ float f32x2_hsum(unsigned long long v) {
    unsigned int lo, hi;
    asm("mov.b64 {%0, %1}, %2;" : "=r"(lo), "=r"(hi) : "l"(v));
    return __uint_as_float(lo) + __uint_as_float(hi);
}

// ---------------- dtype detect ----------------
// int64 little-endian with values < 100000 => every odd 32-bit word is 0.
__global__ void detect_kernel(const int* __restrict__ p) {
    __shared__ int cnt;
    if (threadIdx.x == 0) cnt = 0;
    __syncthreads();
    int nz = 0;
    for (int i = threadIdx.x; i < 4096; i += blockDim.x)
        if (p[2 * i + 1] != 0) nz++;
    atomicAdd(&cnt, nz);
    __syncthreads();
    if (threadIdx.x == 0) g_flag = (cnt < 64) ? 1 : 0;
}

__device__ __forceinline__ int load_idx(const void* eidx, long long i) {
    if (g_flag) return (int)((const long long*)eidx)[i];
    return ((const int*)eidx)[i];
}

// ---------------- single-pass bucket fill (no scan needed) ----------------
__global__ void bucket_kernel(const void* __restrict__ eidx,
                              const float* __restrict__ attr, int E) {
    int e = blockIdx.x * blockDim.x + threadIdx.x;
    if (e >= E) return;
    int s = load_idx(eidx, e);
    int d = load_idx(eidx, (long long)E + e);
    float ex = __expf(attr[e]);
    int pos = atomicAdd(&g_fill[d], 1);
    if (pos < PAD) {
        g_edge[d * PAD + pos] = make_float2(__int_as_float(s), ex);
        atomicAdd(&g_expsum[d], ex);
    }
}

// ---------------- GEMM: XW[n][o] = sum_k X[n][k] * W[o][k] ----------------
// 128-row x 64-col tile, KC=64 k-chunks, 512 threads.
// f32x2 FMAs packed along K-pairs. Thread (rg=tid>>5, cg=tid&31):
// rows 8rg..8rg+7, cols 2cg, 2cg+1 (adjacent -> natural half2 store).
template <int CIN>
__global__ void __launch_bounds__(512) gemm_kernel(
    const float* __restrict__ X, const float* __restrict__ W,
    float* __restrict__ XW, __half* __restrict__ XWH, int N) {
    __shared__ float xs[128][64];                  // [row][k] 32KB
    __shared__ unsigned long long wt2[32][64];     // [k-pair][out] 16KB
    const int tid = threadIdx.x;
    const int cg = tid & 31;
    const int rg = tid >> 5;
    const int base = blockIdx.x * 128;

    unsigned long long acc[8][2] = {};

    for (int kc = 0; kc < CIN; kc += 64) {
        for (int idx = tid; idx < 64 * 16; idx += 512) {
            int o = idx & 63, k4 = idx >> 6;
            float4 w = *(const float4*)(W + o * CIN + kc + k4 * 4);
            unsigned long long p0, p1;
            asm("mov.b64 %0, {%1, %2};" : "=l"(p0) : "f"(w.x), "f"(w.y));
            asm("mov.b64 %0, {%1, %2};" : "=l"(p1) : "f"(w.z), "f"(w.w));
            wt2[2 * k4 + 0][o] = p0;
            wt2[2 * k4 + 1][o] = p1;
        }
        for (int idx = tid; idx < 128 * 16; idx += 512) {
            int r = idx >> 4, k4 = idx & 15;
            int n = base + r;
            float4 v = (n < N) ? *(const float4*)(X + (size_t)n * CIN + kc + k4 * 4)
                               : make_float4(0.f, 0.f, 0.f, 0.f);
            *(float4*)&xs[r][k4 * 4] = v;
        }
        __syncthreads();

#pragma unroll
        for (int k4 = 0; k4 < 16; k4++) {
            unsigned long long b00 = wt2[2 * k4 + 0][2 * cg + 0];
            unsigned long long b01 = wt2[2 * k4 + 0][2 * cg + 1];
            unsigned long long b10 = wt2[2 * k4 + 1][2 * cg + 0];
            unsigned long long b11 = wt2[2 * k4 + 1][2 * cg + 1];
#pragma unroll
            for (int i = 0; i < 8; i++) {
                ulonglong2 a = *(const ulonglong2*)&xs[rg * 8 + i][k4 * 4];
                ffma2(acc[i][0], a.x, b00);
                ffma2(acc[i][0], a.y, b10);
                ffma2(acc[i][1], a.x, b01);
                ffma2(acc[i][1], a.y, b11);
            }
        }
        __syncthreads();
    }

#pragma unroll
    for (int i = 0; i < 8; i++) {
        int n = base + rg * 8 + i;
        if (n < N) {
            float2 r = make_float2(f32x2_hsum(acc[i][0]), f32x2_hsum(acc[i][1]));
            *(float2*)(XW + (size_t)n * 64 + 2 * cg) = r;
            *(__half2*)(XWH + (size_t)n * 64 + 2 * cg) = __float22half2_rn(r);
        }
    }
}

// ---------------- fused aggregate + softmax-div + self + bias + sigmoid ----
// warp per node; lane l owns cols 2l, 2l+1; fp16 gather payload, fp32 math.
__global__ void __launch_bounds__(256) aggregate_kernel(
    const float* __restrict__ XW, const __half* __restrict__ XWH,
    const float* __restrict__ b, float* __restrict__ H, int N) {
    int warp = (blockIdx.x * blockDim.x + threadIdx.x) >> 5;
    int lane = threadIdx.x & 31;
    if (warp >= N) return;
    int n = warp;
    int cnt = g_fill[n];
    if (cnt > PAD) cnt = PAD;
    const float2* ep = g_edge + n * PAD;
    int c = lane * 2;
    float a0 = 0.f, a1 = 0.f;
    int i = 0;
    for (; i + 4 <= cnt; i += 4) {
        float2 e0 = ep[i + 0];
        float2 e1 = ep[i + 1];
        float2 e2 = ep[i + 2];
        float2 e3 = ep[i + 3];
        float2 v0 = __half22float2(*(const __half2*)(XWH + __float_as_int(e0.x) * 64 + c));
        float2 v1 = __half22float2(*(const __half2*)(XWH + __float_as_int(e1.x) * 64 + c));
        float2 v2 = __half22float2(*(const __half2*)(XWH + __float_as_int(e2.x) * 64 + c));
        float2 v3 = __half22float2(*(const __half2*)(XWH + __float_as_int(e3.x) * 64 + c));
        a0 += e0.y * v0.x + e1.y * v1.x + e2.y * v2.x + e3.y * v3.x;
        a1 += e0.y * v0.y + e1.y * v1.y + e2.y * v2.y + e3.y * v3.y;
    }
    for (; i < cnt; i++) {
        float2 e0 = ep[i];
        float2 v0 = __half22float2(*(const __half2*)(XWH + __float_as_int(e0.x) * 64 + c));
        a0 += e0.y * v0.x;
        a1 += e0.y * v0.y;
    }
    float inv = (cnt > 0) ? 1.f / g_expsum[n] : 0.f;
    float2 xn = *(const float2*)(XW + (size_t)n * 64 + c);
    float o0 = a0 * inv + xn.x + b[c];
    float o1 = a1 * inv + xn.y + b[c + 1];
    float2 r;
    r.x = 1.f / (1.f + __expf(-o0));
    r.y = 1.f / (1.f + __expf(-o1));
    *(float2*)(H + (size_t)n * 64 + c) = r;
}

// ---------------- launch ----------------
extern "C" void kernel_launch(void* const* d_in, const int* in_sizes, int n_in,
                              void* d_out, int out_size) {
    const float* x    = (const float*)d_in[0];
    const void*  eidx = d_in[1];
    const float* attr = (const float*)d_in[2];
    const float* W1   = (const float*)d_in[3];
    const float* b1   = (const float*)d_in[4];
    const float* W2   = (const float*)d_in[5];
    const float* b2   = (const float*)d_in[6];
    float* out = (float*)d_out;

    int E = in_sizes[2];           // 1,600,000
    int N = out_size / 64;         // 100,000

    void* p;
    cudaGetSymbolAddress(&p, g_xw);   float*  xw  = (float*)p;
    cudaGetSymbolAddress(&p, g_xwh);  __half* xwh = (__half*)p;
    cudaGetSymbolAddress(&p, g_h1);   float*  h1  = (float*)p;
    void *pe, *pf;
    cudaGetSymbolAddress(&pe, g_expsum);
    cudaGetSymbolAddress(&pf, g_fill);

    int eb = (E + 511) / 512;

    // fork: preprocessing (edge-only) on side stream, gemm1 on main stream
    cudaStream_t s1;
    cudaStreamCreate(&s1);
    cudaEvent_t evFork, evPre;
    cudaEventCreateWithFlags(&evFork, cudaEventDisableTiming);
    cudaEventCreateWithFlags(&evPre, cudaEventDisableTiming);

    cudaEventRecord(evFork, 0);
    cudaStreamWaitEvent(s1, evFork, 0);

    // s1: single-pass CSR + attention preprocessing (shared by both layers)
    cudaMemsetAsync(pe, 0, N * sizeof(float), s1);
    cudaMemsetAsync(pf, 0, N * sizeof(int), s1);
    detect_kernel<<<1, 256, 0, s1>>>((const int*)eidx);
    bucket_kernel<<<eb, 512, 0, s1>>>(eidx, attr, E);
    cudaEventRecord(evPre, s1);

    int gemm_blocks = (N + 127) / 128;
    int agg_blocks  = (N + 7) / 8;   // 8 warps per 256-thread block

    // main stream: layer-1 GEMM overlaps preprocessing
    gemm_kernel<128><<<gemm_blocks, 512>>>(x, W1, xw, xwh, N);

    // join, then the serial tail
    cudaStreamWaitEvent(0, evPre, 0);
    aggregate_kernel<<<agg_blocks, 256>>>(xw, xwh, b1, h1, N);
    gemm_kernel<64><<<gemm_blocks, 512>>>(h1, W2, xw, xwh, N);
    aggregate_kernel<<<agg_blocks, 256>>>(xw, xwh, b2, out, N);
}

// round 5
// speedup vs baseline: 1.4518x; 1.4518x over previous
#include <cuda_runtime.h>
#include <cuda_bf16.h>
#include <cuda_fp16.h>

#define N_MAX 100000
#define E_MAX 1600000

// ---------------- device scratch ----------------
__device__ int    g_flag;                 // 1 = edge_index is int64
__device__ float  g_expsum[N_MAX];
__device__ int    g_count[N_MAX];
__device__ int    g_fill[N_MAX];
__device__ int    g_off[N_MAX + 1];
__device__ int    g_bsum[256];
__device__ float2 g_edge[E_MAX];          // {src_bits, exp(attr)} CSR by dst
__device__ float  g_xw[N_MAX * 64];       // fp32 (self term + next-layer input)
__device__ __half g_xwh[N_MAX * 64];      // fp16 copy (gather payload)
__device__ float  g_h1[N_MAX * 64];

// ---------------- f32x2 packed fma ----------------
__device__ __forceinline__ void ffma2(unsigned long long& d,
                                      unsigned long long a,
                                      unsigned long long b) {
    asm("fma.rn.f32x2 %0, %1, %2, %0;" : "+l"(d) : "l"(a), "l"(b));
}
__device__ __forceinline__ float f32x2_hsum(unsigned long long v) {
    unsigned int lo, hi;
    asm("mov.b64 {%0, %1}, %2;" : "=r"(lo), "=r"(hi) : "l"(v));
    return __uint_as_float(lo) + __uint_as_float(hi);
}

// ---------------- dtype detect ----------------
// int64 little-endian with values < 100000 => every odd 32-bit word is 0.
__global__ void detect_kernel(const int* __restrict__ p) {
    __shared__ int cnt;
    if (threadIdx.x == 0) cnt = 0;
    __syncthreads();
    int nz = 0;
    for (int i = threadIdx.x; i < 4096; i += blockDim.x)
        if (p[2 * i + 1] != 0) nz++;
    atomicAdd(&cnt, nz);
    __syncthreads();
    if (threadIdx.x == 0) g_flag = (cnt < 64) ? 1 : 0;
}

__device__ __forceinline__ int load_idx(const void* eidx, long long i) {
    if (g_flag) return (int)((const long long*)eidx)[i];
    return ((const int*)eidx)[i];
}

// in-degree histogram
__global__ void hist_kernel(const void* __restrict__ eidx, int E) {
    int e = blockIdx.x * blockDim.x + threadIdx.x;
    if (e >= E) return;
    int d = load_idx(eidx, (long long)E + e);
    atomicAdd(&g_count[d], 1);
}

// ---------------- scan (counts -> offsets) ----------------
__global__ void scan1_kernel(int N) {
    __shared__ int s[1024];
    int t = threadIdx.x;
    int i = blockIdx.x * 1024 + t;
    int v = (i < N) ? g_count[i] : 0;
    s[t] = v;
    __syncthreads();
    for (int d2 = 1; d2 < 1024; d2 <<= 1) {
        int w = (t >= d2) ? s[t - d2] : 0;
        __syncthreads();
        s[t] += w;
        __syncthreads();
    }
    if (i < N) g_off[i + 1] = s[t];
    if (t == 1023) g_bsum[blockIdx.x] = s[t];
    if (blockIdx.x == 0 && t == 0) g_off[0] = 0;
}

__global__ void scan2_kernel(int nb) {
    __shared__ int s[256];
    int t = threadIdx.x;
    int v = (t < nb) ? g_bsum[t] : 0;
    s[t] = v;
    __syncthreads();
    for (int d2 = 1; d2 < 256; d2 <<= 1) {
        int w = (t >= d2) ? s[t - d2] : 0;
        __syncthreads();
        s[t] += w;
        __syncthreads();
    }
    if (t < nb) g_bsum[t] = s[t] - v;   // exclusive
}

__global__ void scan3_kernel(int N) {
    int i = blockIdx.x * 1024 + threadIdx.x;
    if (i < N && blockIdx.x > 0) g_off[i + 1] += g_bsum[blockIdx.x];
}

// fill CSR buckets: packed {src, exp(attr)}, accumulate expsum here
__global__ void bucket_kernel(const void* __restrict__ eidx,
                              const float* __restrict__ attr, int E) {
    int e = blockIdx.x * blockDim.x + threadIdx.x;
    if (e >= E) return;
    int s = load_idx(eidx, e);
    int d = load_idx(eidx, (long long)E + e);
    float ex = __expf(attr[e]);
    int pos = g_off[d] + atomicAdd(&g_fill[d], 1);
    g_edge[pos] = make_float2(__int_as_float(s), ex);
    atomicAdd(&g_expsum[d], ex);
}

// ---------------- GEMM: XW[n][o] = sum_k X[n][k] * W[o][k] ----------------
// (round-3 proven version) 128x64 tile, KC=64 chunks, 512 threads, f32x2 FMA.
// Thread (rg=tid>>4, cg=tid&15): rows 4rg..4rg+3, cols cg+16j (j=0..3).
// Also emits fp16 copy XWH for the aggregate gather path.
template <int CIN>
__global__ void __launch_bounds__(512, 2) gemm_kernel(
    const float* __restrict__ X, const float* __restrict__ W,
    float* __restrict__ XW, __half* __restrict__ XWH, int N) {
    __shared__ float xs[128][64];                  // [row][k] 32KB
    __shared__ unsigned long long wt2[32][64];     // [k-pair][out] 16KB
    const int tid = threadIdx.x;
    const int cg = tid & 15;
    const int rg = tid >> 4;
    const int base = blockIdx.x * 128;

    unsigned long long acc[4][4] = {};

    for (int kc = 0; kc < CIN; kc += 64) {
        for (int idx = tid; idx < 64 * 16; idx += 512) {
            int o = idx & 63, k4 = idx >> 6;
            float4 w = *(const float4*)(W + o * CIN + kc + k4 * 4);
            unsigned long long p0, p1;
            asm("mov.b64 %0, {%1, %2};" : "=l"(p0) : "f"(w.x), "f"(w.y));
            asm("mov.b64 %0, {%1, %2};" : "=l"(p1) : "f"(w.z), "f"(w.w));
            wt2[2 * k4 + 0][o] = p0;
            wt2[2 * k4 + 1][o] = p1;
        }
        for (int idx = tid; idx < 128 * 16; idx += 512) {
            int r = idx >> 4, k4 = idx & 15;
            int n = base + r;
            float4 v = (n < N) ? *(const float4*)(X + (size_t)n * CIN + kc + k4 * 4)
                               : make_float4(0.f, 0.f, 0.f, 0.f);
            *(float4*)&xs[r][k4 * 4] = v;
        }
        __syncthreads();

#pragma unroll
        for (int k4 = 0; k4 < 16; k4++) {
            ulonglong2 b[4];
#pragma unroll
            for (int j = 0; j < 4; j++) {
                b[j].x = wt2[2 * k4 + 0][cg + 16 * j];
                b[j].y = wt2[2 * k4 + 1][cg + 16 * j];
            }
#pragma unroll
            for (int i = 0; i < 4; i++) {
                ulonglong2 a = *(const ulonglong2*)&xs[rg * 4 + i][k4 * 4];
#pragma unroll
                for (int j = 0; j < 4; j++) {
                    ffma2(acc[i][j], a.x, b[j].x);
                    ffma2(acc[i][j], a.y, b[j].y);
                }
            }
        }
        __syncthreads();
    }

#pragma unroll
    for (int i = 0; i < 4; i++) {
        int n = base + rg * 4 + i;
        if (n < N) {
#pragma unroll
            for (int j = 0; j < 4; j++) {
                float r = f32x2_hsum(acc[i][j]);
                XW[(size_t)n * 64 + cg + 16 * j] = r;
                XWH[(size_t)n * 64 + cg + 16 * j] = __float2half_rn(r);
            }
        }
    }
}

// ---------------- fused aggregate + softmax-div + self + bias + sigmoid ----
// warp per node; lane l owns cols 2l,2l+1. fp16 gather payload, fp32 math.
// Edges consumed 2-per-LDG via float4 (CSR base is 16B aligned; even-i only).
__global__ void __launch_bounds__(256) aggregate_kernel(
    const float* __restrict__ XW, const __half* __restrict__ XWH,
    const float* __restrict__ b, float* __restrict__ H, int N) {
    int warp = (blockIdx.x * blockDim.x + threadIdx.x) >> 5;
    int lane = threadIdx.x & 31;
    if (warp >= N) return;
    int n = warp;
    int i0 = g_off[n], i1 = g_off[n + 1];
    int c = lane * 2;
    float a0 = 0.f, a1 = 0.f;
    int i = i0;
    // alignment prologue: make i even so (g_edge + i) is 16B aligned
    if ((i & 1) && i < i1) {
        float2 e = g_edge[i];
        float2 v = __half22float2(*(const __half2*)(XWH + __float_as_int(e.x) * 64 + c));
        a0 += e.y * v.x; a1 += e.y * v.y;
        i++;
    }
    for (; i + 4 <= i1; i += 4) {
        float4 p = *(const float4*)(g_edge + i);       // edges i, i+1
        float4 q = *(const float4*)(g_edge + i + 2);   // edges i+2, i+3
        float2 v0 = __half22float2(*(const __half2*)(XWH + __float_as_int(p.x) * 64 + c));
        float2 v1 = __half22float2(*(const __half2*)(XWH + __float_as_int(p.z) * 64 + c));
        float2 v2 = __half22float2(*(const __half2*)(XWH + __float_as_int(q.x) * 64 + c));
        float2 v3 = __half22float2(*(const __half2*)(XWH + __float_as_int(q.z) * 64 + c));
        a0 += p.y * v0.x + p.w * v1.x + q.y * v2.x + q.w * v3.x;
        a1 += p.y * v0.y + p.w * v1.y + q.y * v2.y + q.w * v3.y;
    }
    if (i + 2 <= i1) {
        float4 p = *(const float4*)(g_edge + i);
        float2 v0 = __half22float2(*(const __half2*)(XWH + __float_as_int(p.x) * 64 + c));
        float2 v1 = __half22float2(*(const __half2*)(XWH + __float_as_int(p.z) * 64 + c));
        a0 += p.y * v0.x + p.w * v1.x;
        a1 += p.y * v0.y + p.w * v1.y;
        i += 2;
    }
    if (i < i1) {
        float2 e = g_edge[i];
        float2 v = __half22float2(*(const __half2*)(XWH + __float_as_int(e.x) * 64 + c));
        a0 += e.y * v.x; a1 += e.y * v.y;
    }
    float inv = (i1 > i0) ? 1.f / g_expsum[n] : 0.f;
    float2 xn = *(const float2*)(XW + (size_t)n * 64 + c);
    float o0 = a0 * inv + xn.x + b[c];
    float o1 = a1 * inv + xn.y + b[c + 1];
    float2 r;
    r.x = 1.f / (1.f + __expf(-o0));
    r.y = 1.f / (1.f + __expf(-o1));
    *(float2*)(H + (size_t)n * 64 + c) = r;
}

// ---------------- launch ----------------
extern "C" void kernel_launch(void* const* d_in, const int* in_sizes, int n_in,
                              void* d_out, int out_size) {
    const float* x    = (const float*)d_in[0];
    const void*  eidx = d_in[1];
    const float* attr = (const float*)d_in[2];
    const float* W1   = (const float*)d_in[3];
    const float* b1   = (const float*)d_in[4];
    const float* W2   = (const float*)d_in[5];
    const float* b2   = (const float*)d_in[6];
    float* out = (float*)d_out;

    int E = in_sizes[2];           // 1,600,000
    int N = out_size / 64;         // 100,000

    void* p;
    cudaGetSymbolAddress(&p, g_xw);   float*  xw  = (float*)p;
    cudaGetSymbolAddress(&p, g_xwh);  __half* xwh = (__half*)p;
    cudaGetSymbolAddress(&p, g_h1);   float*  h1  = (float*)p;
    void *pe, *pc, *pf;
    cudaGetSymbolAddress(&pe, g_expsum);
    cudaGetSymbolAddress(&pc, g_count);
    cudaGetSymbolAddress(&pf, g_fill);

    int eb = (E + 255) / 256;
    int nb = (N + 1023) / 1024;

    // fork: preprocessing (edge-only) on side stream, gemm1 on main stream
    cudaStream_t s1;
    cudaStreamCreate(&s1);
    cudaEvent_t evFork, evPre;
    cudaEventCreateWithFlags(&evFork, cudaEventDisableTiming);
    cudaEventCreateWithFlags(&evPre, cudaEventDisableTiming);

    cudaEventRecord(evFork, 0);
    cudaStreamWaitEvent(s1, evFork, 0);

    // s1: CSR + attention preprocessing (identical across layers)
    cudaMemsetAsync(pe, 0, N * sizeof(float), s1);
    cudaMemsetAsync(pc, 0, N * sizeof(int), s1);
    cudaMemsetAsync(pf, 0, N * sizeof(int), s1);
    detect_kernel<<<1, 256, 0, s1>>>((const int*)eidx);
    hist_kernel<<<eb, 256, 0, s1>>>(eidx, E);
    scan1_kernel<<<nb, 1024, 0, s1>>>(N);
    scan2_kernel<<<1, 256, 0, s1>>>(nb);
    scan3_kernel<<<nb, 1024, 0, s1>>>(N);
    bucket_kernel<<<eb, 256, 0, s1>>>(eidx, attr, E);
    cudaEventRecord(evPre, s1);

    int gemm_blocks = (N + 127) / 128;
    int agg_blocks  = (N + 7) / 8;   // 8 warps per 256-thread block

    // main stream: layer-1 GEMM overlaps preprocessing
    gemm_kernel<128><<<gemm_blocks, 512>>>(x, W1, xw, xwh, N);

    // join, then the serial tail
    cudaStreamWaitEvent(0, evPre, 0);
    aggregate_kernel<<<agg_blocks, 256>>>(xw, xwh, b1, h1, N);
    gemm_kernel<64><<<gemm_blocks, 512>>>(h1, W2, xw, xwh, N);
    aggregate_kernel<<<agg_blocks, 256>>>(xw, xwh, b2, out, N);
}